// round 7
// baseline (speedup 1.0000x reference)
#include <cuda_runtime.h>

#define Bsz 65536
#define DIN 32
#define HID 128
#define LAT 32
#define NC  8
#define KC  512
#define MID 16

// ---------------- scratch (no allocations allowed) ----------------
static __device__ float  g_v[Bsz * LAT];     // 8 MB
static __device__ float  g_hg[Bsz * HID];    // 32 MB
static __device__ float  g_zt[Bsz * LAT];    // 8 MB
static __device__ float  g_cbn[NC * KC];
static __device__ double g_vq;

// ---------------- output layout (concatenated tuple, f32) ----------------
#define O_XHAT 0
#define O_VQ   (Bsz * DIN)
#define O_ENC  (O_VQ + 1)
#define O_DEC  (O_ENC + Bsz * NC)
#define O_K    (O_DEC + Bsz * NC)
#define O_ZGEO (O_K + Bsz)
#define O_ZN   (O_ZGEO + Bsz * LAT)
#define O_CBAR (O_ZN + Bsz * LAT)
#define O_TOTAL (O_CBAR + Bsz * LAT)

// gelu exactly as XLA lowers jax.nn.gelu(approximate=False):
// (0.5*x) * (1 + erf(x / sqrt(2))), true division, no contraction
__device__ __forceinline__ float gelu_ref(float x) {
    float u = __fdiv_rn(x, 1.4142135623730951f);
    float t = erff(u);
    return __fmul_rn(__fmul_rn(0.5f, x), __fadd_rn(1.0f, t));
}

// ---------------- prep: codebook norms + zero vq accumulator ----------------
__global__ void kPrep(const float* __restrict__ cbk) {
    int idx = blockIdx.x * blockDim.x + threadIdx.x;
    if (idx == 0) g_vq = 0.0;
    if (idx < NC * KC) {
        const float* row = cbk + (size_t)idx * LAT;
        float s = 0.f;
        #pragma unroll
        for (int l = 0; l < LAT; l++) s = __fadd_rn(s, __fmul_rn(row[l], row[l]));
        g_cbn[idx] = s;
    }
}

// ---------------- kernel A: x -> features -> v ----------------
__global__ void __launch_bounds__(256) kA(
    const float* __restrict__ x,  const float* __restrict__ w1, const float* __restrict__ b1,
    const float* __restrict__ w2, const float* __restrict__ b2,
    const float* __restrict__ vp, const float* __restrict__ vpb)
{
    extern __shared__ float sm[];
    float* w1n  = sm;                 // [DIN][HID] natural   4096 f
    float* w2n  = w1n + DIN * HID;    // [HID][HID] natural  16384 f
    float* vps  = w2n + HID * HID;    // [HID][LAT] natural   4096 f
    float* b1s  = vps + HID * LAT;    // 128
    float* b2s  = b1s + HID;          // 128
    float* vpbs = b2s + HID;          // 32
    float* h1s  = vpbs + LAT;         // [HID][256] staging  32768 f

    int tid = threadIdx.x;
    for (int i = tid; i < DIN * HID; i += 256) w1n[i] = w1[i];
    for (int i = tid; i < HID * HID; i += 256) w2n[i] = w2[i];
    for (int i = tid; i < HID * LAT; i += 256) vps[i] = vp[i];
    if (tid < HID) { b1s[tid] = b1[tid]; b2s[tid] = b2[tid]; }
    if (tid < LAT) vpbs[tid] = vpb[tid];
    __syncthreads();

    size_t r = (size_t)blockIdx.x * 256 + tid;

    float xr[DIN];
    {
        const float4* xp = (const float4*)(x + r * DIN);
        #pragma unroll
        for (int i = 0; i < 8; i++) {
            float4 t = xp[i];
            xr[4*i] = t.x; xr[4*i+1] = t.y; xr[4*i+2] = t.z; xr[4*i+3] = t.w;
        }
    }

    // phase 1: h1_j = gelu(seqdot_i(x_i * w1[i][j]) + b1_j); 4 independent chains
    for (int j = 0; j < HID; j += 4) {
        float a0 = 0.f, a1 = 0.f, a2 = 0.f, a3 = 0.f;
        #pragma unroll
        for (int i = 0; i < DIN; i++) {
            float xi = xr[i];
            float4 w = *(const float4*)(w1n + i * HID + j);
            a0 = fmaf(xi, w.x, a0); a1 = fmaf(xi, w.y, a1);
            a2 = fmaf(xi, w.z, a2); a3 = fmaf(xi, w.w, a3);
        }
        h1s[(j+0) * 256 + tid] = gelu_ref(__fadd_rn(a0, b1s[j+0]));
        h1s[(j+1) * 256 + tid] = gelu_ref(__fadd_rn(a1, b1s[j+1]));
        h1s[(j+2) * 256 + tid] = gelu_ref(__fadd_rn(a2, b1s[j+2]));
        h1s[(j+3) * 256 + tid] = gelu_ref(__fadd_rn(a3, b1s[j+3]));
    }

    float h1[HID];
    #pragma unroll
    for (int i = 0; i < HID; i++) h1[i] = h1s[i * 256 + tid];

    // phase 2: h2_j = gelu(seqdot + b2); v_l = seqsum_j h2_j*vp[j][l]; + vpb at end
    float vv[LAT];
    #pragma unroll
    for (int l = 0; l < LAT; l++) vv[l] = 0.f;
    for (int j = 0; j < HID; j += 4) {
        float a0 = 0.f, a1 = 0.f, a2 = 0.f, a3 = 0.f;
        #pragma unroll
        for (int i = 0; i < HID; i++) {
            float hi = h1[i];
            float4 w = *(const float4*)(w2n + i * HID + j);
            a0 = fmaf(hi, w.x, a0); a1 = fmaf(hi, w.y, a1);
            a2 = fmaf(hi, w.z, a2); a3 = fmaf(hi, w.w, a3);
        }
        float u0 = gelu_ref(__fadd_rn(a0, b2s[j+0]));
        float u1 = gelu_ref(__fadd_rn(a1, b2s[j+1]));
        float u2 = gelu_ref(__fadd_rn(a2, b2s[j+2]));
        float u3 = gelu_ref(__fadd_rn(a3, b2s[j+3]));
        const float4* vr0 = (const float4*)(vps + (j+0) * LAT);
        const float4* vr1 = (const float4*)(vps + (j+1) * LAT);
        const float4* vr2 = (const float4*)(vps + (j+2) * LAT);
        const float4* vr3 = (const float4*)(vps + (j+3) * LAT);
        #pragma unroll
        for (int l4 = 0; l4 < 8; l4++) {
            float4 w = vr0[l4];
            vv[4*l4]   = fmaf(u0, w.x, vv[4*l4]);   vv[4*l4+1] = fmaf(u0, w.y, vv[4*l4+1]);
            vv[4*l4+2] = fmaf(u0, w.z, vv[4*l4+2]); vv[4*l4+3] = fmaf(u0, w.w, vv[4*l4+3]);
        }
        #pragma unroll
        for (int l4 = 0; l4 < 8; l4++) {
            float4 w = vr1[l4];
            vv[4*l4]   = fmaf(u1, w.x, vv[4*l4]);   vv[4*l4+1] = fmaf(u1, w.y, vv[4*l4+1]);
            vv[4*l4+2] = fmaf(u1, w.z, vv[4*l4+2]); vv[4*l4+3] = fmaf(u1, w.w, vv[4*l4+3]);
        }
        #pragma unroll
        for (int l4 = 0; l4 < 8; l4++) {
            float4 w = vr2[l4];
            vv[4*l4]   = fmaf(u2, w.x, vv[4*l4]);   vv[4*l4+1] = fmaf(u2, w.y, vv[4*l4+1]);
            vv[4*l4+2] = fmaf(u2, w.z, vv[4*l4+2]); vv[4*l4+3] = fmaf(u2, w.w, vv[4*l4+3]);
        }
        #pragma unroll
        for (int l4 = 0; l4 < 8; l4++) {
            float4 w = vr3[l4];
            vv[4*l4]   = fmaf(u3, w.x, vv[4*l4]);   vv[4*l4+1] = fmaf(u3, w.y, vv[4*l4+1]);
            vv[4*l4+2] = fmaf(u3, w.z, vv[4*l4+2]); vv[4*l4+3] = fmaf(u3, w.w, vv[4*l4+3]);
        }
    }
    float4* vo = (float4*)(g_v + r * LAT);
    #pragma unroll
    for (int l4 = 0; l4 < 8; l4++) {
        float4 t;
        t.x = __fadd_rn(vv[4*l4],   vpbs[4*l4]);
        t.y = __fadd_rn(vv[4*l4+1], vpbs[4*l4+1]);
        t.z = __fadd_rn(vv[4*l4+2], vpbs[4*l4+2]);
        t.w = __fadd_rn(vv[4*l4+3], vpbs[4*l4+3]);
        vo[l4] = t;
    }
}

// ---------------- kernel B: v -> VQ / charts / decoder mix ----------------
__global__ void __launch_bounds__(256) kB(
    const float* __restrict__ cc,   const float* __restrict__ cbk,
    const float* __restrict__ sfw1, const float* __restrict__ sfb1,
    const float* __restrict__ sfw2, const float* __restrict__ sfb2,
    const float* __restrict__ decw, const float* __restrict__ decb,
    const float* __restrict__ lrw,  const float* __restrict__ lrb,
    float* __restrict__ out, int full)
{
    extern __shared__ float sm[];
    float* decws = sm;                       // 32768 f
    float* decbs = decws + NC * HID * LAT;   // 1024 f
    float* cbs   = decbs + NC * HID;         // 16384 f (one chart tile)
    float* cbns  = cbs + KC * LAT;           // 512
    float* ccs   = cbns + KC;                // 256  [c][l]
    float* cct   = ccs + NC * LAT;           // 256  [l][c]
    float* sfw1t = cct + LAT * NC;           // 512 [MID][LAT]
    float* sfw2s = sfw1t + LAT * MID;        // 512 [MID][LAT]
    float* lrws  = sfw2s + MID * LAT;        // 256 [l][c]
    float* sfb1s = lrws + LAT * NC;          // 16
    float* sfb2s = sfb1s + MID;              // 32
    float* lrbs  = sfb2s + LAT;              // 8

    __shared__ float red[256];

    int tid = threadIdx.x;
    for (int i = tid; i < NC * HID * LAT; i += 256) decws[i] = decw[i];
    for (int i = tid; i < NC * HID; i += 256) decbs[i] = decb[i];
    for (int i = tid; i < NC * LAT; i += 256) {
        float t = cc[i]; ccs[i] = t;
        int c = i / LAT, l = i % LAT;
        cct[l * NC + c] = t;
    }
    for (int i = tid; i < LAT * MID; i += 256) { int l = i / MID, m = i % MID; sfw1t[m * LAT + l] = sfw1[i]; }
    for (int i = tid; i < MID * LAT; i += 256) sfw2s[i] = sfw2[i];
    for (int i = tid; i < LAT * NC; i += 256) lrws[i] = lrw[i];
    if (tid < MID) sfb1s[tid] = sfb1[tid];
    if (tid < LAT) sfb2s[tid] = sfb2[tid];
    if (tid < NC)  lrbs[tid] = lrb[tid];

    size_t r = (size_t)blockIdx.x * 256 + tid;

    float v[LAT];
    {
        const float4* vp4 = (const float4*)(g_v + r * LAT);
        #pragma unroll
        for (int i = 0; i < 8; i++) {
            float4 t = vp4[i];
            v[4*i] = t.x; v[4*i+1] = t.y; v[4*i+2] = t.z; v[4*i+3] = t.w;
        }
    }
    __syncthreads();

    // scores -> softmax. e computed via double-precision exp rounded to fp32
    // (= correctly-rounded fp32 exp): CUDA expf's 2-ulp error widens the
    // exp(-g)->1.0f collapse band vs the reference's correctly-rounded exp,
    // which is what desynchronized the argmax tie set. K = first-wins argmax
    // over the correctly-rounded e (jnp.argmax comparator: min index on equal).
    float enc[NC]; int K;
    {
        float sc[NC];
        #pragma unroll
        for (int c = 0; c < NC; c++) sc[c] = 0.f;
        #pragma unroll
        for (int l = 0; l < LAT; l++) {
            float vl = v[l];
            float4 wa = ((const float4*)(cct + l * NC))[0];
            float4 wb = ((const float4*)(cct + l * NC))[1];
            sc[0] = fmaf(vl, wa.x, sc[0]); sc[1] = fmaf(vl, wa.y, sc[1]);
            sc[2] = fmaf(vl, wa.z, sc[2]); sc[3] = fmaf(vl, wa.w, sc[3]);
            sc[4] = fmaf(vl, wb.x, sc[4]); sc[5] = fmaf(vl, wb.y, sc[5]);
            sc[6] = fmaf(vl, wb.z, sc[6]); sc[7] = fmaf(vl, wb.w, sc[7]);
        }
        #pragma unroll
        for (int c = 0; c < NC; c++) sc[c] = __fdiv_rn(sc[c], 5.656854249492381f);
        float m = sc[0];
        #pragma unroll
        for (int c = 1; c < NC; c++) m = fmaxf(m, sc[c]);
        float e[NC];
        #pragma unroll
        for (int c = 0; c < NC; c++)
            e[c] = (float)exp((double)__fsub_rn(sc[c], m));  // correctly-rounded fp32 exp
        float s01 = __fadd_rn(e[0], e[1]);
        float s23 = __fadd_rn(e[2], e[3]);
        float s45 = __fadd_rn(e[4], e[5]);
        float s67 = __fadd_rn(e[6], e[7]);
        float s = __fadd_rn(__fadd_rn(s01, s23), __fadd_rn(s45, s67));
        #pragma unroll
        for (int c = 0; c < NC; c++) enc[c] = __fdiv_rn(e[c], s);
        // FIRST-wins argmax over e (strict >)
        float bm = e[0]; K = 0;
        #pragma unroll
        for (int c = 1; c < NC; c++) if (e[c] > bm) { bm = e[c]; K = c; }
    }

    // c_bar: seq-fma over c per l; v_local = v - c_bar (plain sub)
    float cb[LAT];
    #pragma unroll
    for (int l = 0; l < LAT; l++) cb[l] = 0.f;
    #pragma unroll
    for (int c = 0; c < NC; c++) {
        float e = enc[c];
        #pragma unroll
        for (int l = 0; l < LAT; l++) cb[l] = fmaf(e, ccs[c * LAT + l], cb[l]);
    }
    #pragma unroll
    for (int l = 0; l < LAT; l++) v[l] = __fsub_rn(v[l], cb[l]);   // v is now v_local

    // ||v_local||^2: separate multiply + sequential add (jnp.sum(v*v))
    float vn = 0.f;
    #pragma unroll
    for (int l = 0; l < LAT; l++) vn = __fadd_rn(vn, __fmul_rn(v[l], v[l]));

    // VQ argmin per chart; dot seq-fma over l, dist = (vn - 2e) + cbn,
    // strict < first-wins. 4 independent k-chains for ILP.
    int bidx[NC];
    #pragma unroll
    for (int c = 0; c < NC; c++) {
        __syncthreads();
        const float* src = cbk + (size_t)c * KC * LAT;
        for (int i = tid; i < KC * LAT; i += 256) cbs[i] = src[i];
        for (int i = tid; i < KC; i += 256) cbns[i] = g_cbn[c * KC + i];
        __syncthreads();
        float best = 3.4e38f; int bi = 0;
        for (int k = 0; k < KC; k += 4) {
            float e0 = 0.f, e1 = 0.f, e2 = 0.f, e3 = 0.f;
            const float4* r0 = (const float4*)(cbs + (k+0) * LAT);
            const float4* r1 = (const float4*)(cbs + (k+1) * LAT);
            const float4* r2 = (const float4*)(cbs + (k+2) * LAT);
            const float4* r3 = (const float4*)(cbs + (k+3) * LAT);
            #pragma unroll
            for (int i = 0; i < 8; i++) {
                float4 w0 = r0[i], w1 = r1[i], w2 = r2[i], w3 = r3[i];
                e0 = fmaf(v[4*i], w0.x, e0); e0 = fmaf(v[4*i+1], w0.y, e0);
                e0 = fmaf(v[4*i+2], w0.z, e0); e0 = fmaf(v[4*i+3], w0.w, e0);
                e1 = fmaf(v[4*i], w1.x, e1); e1 = fmaf(v[4*i+1], w1.y, e1);
                e1 = fmaf(v[4*i+2], w1.z, e1); e1 = fmaf(v[4*i+3], w1.w, e1);
                e2 = fmaf(v[4*i], w2.x, e2); e2 = fmaf(v[4*i+1], w2.y, e2);
                e2 = fmaf(v[4*i+2], w2.z, e2); e2 = fmaf(v[4*i+3], w2.w, e2);
                e3 = fmaf(v[4*i], w3.x, e3); e3 = fmaf(v[4*i+1], w3.y, e3);
                e3 = fmaf(v[4*i+2], w3.z, e3); e3 = fmaf(v[4*i+3], w3.w, e3);
            }
            float d0 = __fadd_rn(__fsub_rn(vn, __fmul_rn(2.0f, e0)), cbns[k+0]);
            float d1 = __fadd_rn(__fsub_rn(vn, __fmul_rn(2.0f, e1)), cbns[k+1]);
            float d2 = __fadd_rn(__fsub_rn(vn, __fmul_rn(2.0f, e2)), cbns[k+2]);
            float d3 = __fadd_rn(__fsub_rn(vn, __fmul_rn(2.0f, e3)), cbns[k+3]);
            if (d0 < best) { best = d0; bi = k+0; }
            if (d1 < best) { best = d1; bi = k+1; }
            if (d2 < best) { best = d2; bi = k+2; }
            if (d3 < best) { best = d3; bi = k+3; }
        }
        bidx[c] = bi;
    }

    // gather z_q, vq partial, z_q_blended, SF MLP -> z_n
    float zqb[LAT], zn[LAT];
    #pragma unroll
    for (int l = 0; l < LAT; l++) { zqb[l] = 0.f; zn[l] = 0.f; }
    float vqa = 0.f;
    #pragma unroll
    for (int c = 0; c < NC; c++) {
        float zq[LAT];
        {
            const float4* z4 = (const float4*)(cbk + ((size_t)c * KC + bidx[c]) * LAT);
            #pragma unroll
            for (int i = 0; i < 8; i++) {
                float4 t = z4[i];
                zq[4*i] = t.x; zq[4*i+1] = t.y; zq[4*i+2] = t.z; zq[4*i+3] = t.w;
            }
        }
        float e = enc[c];
        #pragma unroll
        for (int l = 0; l < LAT; l++) zqb[l] = fmaf(e, zq[l], zqb[l]);
        float sq = 0.f;
        #pragma unroll
        for (int l = 0; l < LAT; l++) { float d = __fsub_rn(v[l], zq[l]); zq[l] = d; sq = fmaf(d, d, sq); }
        vqa = fmaf(e, sq, vqa);
        // zq now holds delta
        float mv[MID];
        #pragma unroll
        for (int m = 0; m < MID; m++) {
            float a = 0.f;
            const float4* w4 = (const float4*)(sfw1t + m * LAT);
            #pragma unroll
            for (int i = 0; i < 8; i++) {
                float4 w = w4[i];
                a = fmaf(zq[4*i], w.x, a); a = fmaf(zq[4*i+1], w.y, a);
                a = fmaf(zq[4*i+2], w.z, a); a = fmaf(zq[4*i+3], w.w, a);
            }
            mv[m] = gelu_ref(__fadd_rn(a, sfb1s[m]));
        }
        #pragma unroll
        for (int l4 = 0; l4 < 8; l4++) {
            float4 acc = make_float4(0.f, 0.f, 0.f, 0.f);
            #pragma unroll
            for (int m = 0; m < MID; m++) {
                float4 w = ((const float4*)sfw2s)[m * 8 + l4];
                acc.x = fmaf(mv[m], w.x, acc.x); acc.y = fmaf(mv[m], w.y, acc.y);
                acc.z = fmaf(mv[m], w.z, acc.z); acc.w = fmaf(mv[m], w.w, acc.w);
            }
            float4 b = ((const float4*)sfb2s)[l4];
            zn[4*l4]   = fmaf(e, __fadd_rn(acc.x, b.x), zn[4*l4]);
            zn[4*l4+1] = fmaf(e, __fadd_rn(acc.y, b.y), zn[4*l4+1]);
            zn[4*l4+2] = fmaf(e, __fadd_rn(acc.z, b.z), zn[4*l4+2]);
            zn[4*l4+3] = fmaf(e, __fadd_rn(acc.w, b.w), zn[4*l4+3]);
        }
    }

    // z_geo / zg / z_tex; write outputs
    float zg[LAT];
    #pragma unroll
    for (int l = 0; l < LAT; l++) {
        float zgeo = __fadd_rn(__fadd_rn(cb[l], zqb[l]), zn[l]);
        zg[l] = tanhf(zgeo);
        float ztv = tanhf(__fsub_rn(__fsub_rn(v[l], zqb[l]), zn[l]));
        g_zt[r * LAT + l] = ztv;
        if (full) {
            out[O_ZGEO + r * LAT + l] = zgeo;
            out[O_ZN   + r * LAT + l] = zn[l];
            out[O_CBAR + r * LAT + l] = cb[l];
        }
    }

    // dec_rw softmax: seq-fma over l, +bias AFTER, true divisions
    float dec[NC];
    {
        float lg[NC];
        #pragma unroll
        for (int c = 0; c < NC; c++) lg[c] = 0.f;
        #pragma unroll
        for (int l = 0; l < LAT; l++) {
            float zl = zg[l];
            #pragma unroll
            for (int c = 0; c < NC; c++) lg[c] = fmaf(zl, lrws[l * NC + c], lg[c]);
        }
        #pragma unroll
        for (int c = 0; c < NC; c++) lg[c] = __fadd_rn(lg[c], lrbs[c]);
        float m = lg[0];
        #pragma unroll
        for (int c = 1; c < NC; c++) m = fmaxf(m, lg[c]);
        float s = 0.f;
        #pragma unroll
        for (int c = 0; c < NC; c++) { dec[c] = expf(__fsub_rn(lg[c], m)); s = __fadd_rn(s, dec[c]); }
        #pragma unroll
        for (int c = 0; c < NC; c++) dec[c] = __fdiv_rn(dec[c], s);
    }
    if (full) {
        #pragma unroll
        for (int c = 0; c < NC; c++) {
            out[O_ENC + r * NC + c] = enc[c];
            out[O_DEC + r * NC + c] = dec[c];
        }
        out[O_K + r] = (float)K;
    }

    // h_global: per (c,h): seq-fma dot over l, +decb after; weighted sum over c
    for (int h = 0; h < HID; h++) {
        float acc = 0.f;
        #pragma unroll
        for (int c = 0; c < NC; c++) {
            float a = 0.f;
            const float4* w4 = (const float4*)(decws + (c * HID + h) * LAT);
            #pragma unroll
            for (int i = 0; i < 8; i++) {
                float4 w = w4[i];
                a = fmaf(zg[4*i], w.x, a); a = fmaf(zg[4*i+1], w.y, a);
                a = fmaf(zg[4*i+2], w.z, a); a = fmaf(zg[4*i+3], w.w, a);
            }
            acc = __fadd_rn(acc, __fmul_rn(dec[c], __fadd_rn(a, decbs[c * HID + h])));
        }
        g_hg[r * HID + h] = acc;
    }

    // vq partial reduce
    red[tid] = vqa;
    __syncthreads();
    for (int s = 128; s > 0; s >>= 1) {
        if (tid < s) red[tid] += red[tid + s];
        __syncthreads();
    }
    if (tid == 0) atomicAdd(&g_vq, (double)red[0]);
}

// ---------------- kernel C: h_global -> x_hat ----------------
__global__ void __launch_bounds__(256) kC(
    const float* __restrict__ rw1, const float* __restrict__ rb1,
    const float* __restrict__ rw2, const float* __restrict__ rb2,
    const float* __restrict__ skw, const float* __restrict__ skb,
    const float* __restrict__ txw, const float* __restrict__ txb,
    const float* __restrict__ tscale, float* __restrict__ out)
{
    extern __shared__ float sm[];
    float* rw1n = sm;                 // [i][j] natural 16384 f
    float* rw2s = rw1n + HID * HID;   // 4096 f
    float* skws = rw2s + HID * DIN;   // 4096 f
    float* txws = skws + HID * DIN;   // 1024 f
    float* rb1s = txws + LAT * DIN;   // 128
    float* rb2s = rb1s + HID;         // 32
    float* skbs = rb2s + DIN;         // 32
    float* txbs = skbs + DIN;         // 32

    int tid = threadIdx.x;
    for (int i = tid; i < HID * HID; i += 256) rw1n[i] = rw1[i];
    for (int i = tid; i < HID * DIN; i += 256) { rw2s[i] = rw2[i]; skws[i] = skw[i]; }
    for (int i = tid; i < LAT * DIN; i += 256) txws[i] = txw[i];
    if (tid < HID) rb1s[tid] = rb1[tid];
    if (tid < DIN) { rb2s[tid] = rb2[tid]; skbs[tid] = skb[tid]; txbs[tid] = txb[tid]; }
    __syncthreads();

    size_t r = (size_t)blockIdx.x * 256 + tid;
    float ts = tscale[0];

    const float* hgp = g_hg + r * HID;

    // g = gelu(h_global); also keep h for skip path
    float hg[HID], g[HID];
    {
        const float4* h4 = (const float4*)hgp;
        #pragma unroll
        for (int i = 0; i < 32; i++) {
            float4 t = h4[i];
            hg[4*i] = t.x; hg[4*i+1] = t.y; hg[4*i+2] = t.z; hg[4*i+3] = t.w;
            g[4*i]   = gelu_ref(t.x); g[4*i+1] = gelu_ref(t.y);
            g[4*i+2] = gelu_ref(t.z); g[4*i+3] = gelu_ref(t.w);
        }
    }

    float o[DIN], sk[DIN];
    #pragma unroll
    for (int l = 0; l < DIN; l++) { o[l] = 0.f; sk[l] = 0.f; }

    // h1r = gelu(g @ rw1 + rb1); o = h1r @ rw2 (4 j-chains at a time)
    for (int j = 0; j < HID; j += 4) {
        float a0 = 0.f, a1 = 0.f, a2 = 0.f, a3 = 0.f;
        #pragma unroll
        for (int i = 0; i < HID; i++) {
            float gi = g[i];
            float4 w = *(const float4*)(rw1n + i * HID + j);
            a0 = fmaf(gi, w.x, a0); a1 = fmaf(gi, w.y, a1);
            a2 = fmaf(gi, w.z, a2); a3 = fmaf(gi, w.w, a3);
        }
        float u0 = gelu_ref(__fadd_rn(a0, rb1s[j+0]));
        float u1 = gelu_ref(__fadd_rn(a1, rb1s[j+1]));
        float u2 = gelu_ref(__fadd_rn(a2, rb1s[j+2]));
        float u3 = gelu_ref(__fadd_rn(a3, rb1s[j+3]));
        const float4* r0 = (const float4*)(rw2s + (j+0) * DIN);
        const float4* r1 = (const float4*)(rw2s + (j+1) * DIN);
        const float4* r2 = (const float4*)(rw2s + (j+2) * DIN);
        const float4* r3 = (const float4*)(rw2s + (j+3) * DIN);
        #pragma unroll
        for (int l4 = 0; l4 < 8; l4++) {
            float4 w = r0[l4];
            o[4*l4]   = fmaf(u0, w.x, o[4*l4]);   o[4*l4+1] = fmaf(u0, w.y, o[4*l4+1]);
            o[4*l4+2] = fmaf(u0, w.z, o[4*l4+2]); o[4*l4+3] = fmaf(u0, w.w, o[4*l4+3]);
        }
        #pragma unroll
        for (int l4 = 0; l4 < 8; l4++) {
            float4 w = r1[l4];
            o[4*l4]   = fmaf(u1, w.x, o[4*l4]);   o[4*l4+1] = fmaf(u1, w.y, o[4*l4+1]);
            o[4*l4+2] = fmaf(u1, w.z, o[4*l4+2]); o[4*l4+3] = fmaf(u1, w.w, o[4*l4+3]);
        }
        #pragma unroll
        for (int l4 = 0; l4 < 8; l4++) {
            float4 w = r2[l4];
            o[4*l4]   = fmaf(u2, w.x, o[4*l4]);   o[4*l4+1] = fmaf(u2, w.y, o[4*l4+1]);
            o[4*l4+2] = fmaf(u2, w.z, o[4*l4+2]); o[4*l4+3] = fmaf(u2, w.w, o[4*l4+3]);
        }
        #pragma unroll
        for (int l4 = 0; l4 < 8; l4++) {
            float4 w = r3[l4];
            o[4*l4]   = fmaf(u3, w.x, o[4*l4]);   o[4*l4+1] = fmaf(u3, w.y, o[4*l4+1]);
            o[4*l4+2] = fmaf(u3, w.z, o[4*l4+2]); o[4*l4+3] = fmaf(u3, w.w, o[4*l4+3]);
        }
        // skip path: same j ordering
        const float4* s0 = (const float4*)(skws + (j+0) * DIN);
        const float4* s1 = (const float4*)(skws + (j+1) * DIN);
        const float4* s2 = (const float4*)(skws + (j+2) * DIN);
        const float4* s3 = (const float4*)(skws + (j+3) * DIN);
        float h0 = hg[j+0], h1v = hg[j+1], h2v = hg[j+2], h3v = hg[j+3];
        #pragma unroll
        for (int l4 = 0; l4 < 8; l4++) {
            float4 w = s0[l4];
            sk[4*l4]   = fmaf(h0, w.x, sk[4*l4]);   sk[4*l4+1] = fmaf(h0, w.y, sk[4*l4+1]);
            sk[4*l4+2] = fmaf(h0, w.z, sk[4*l4+2]); sk[4*l4+3] = fmaf(h0, w.w, sk[4*l4+3]);
        }
        #pragma unroll
        for (int l4 = 0; l4 < 8; l4++) {
            float4 w = s1[l4];
            sk[4*l4]   = fmaf(h1v, w.x, sk[4*l4]);   sk[4*l4+1] = fmaf(h1v, w.y, sk[4*l4+1]);
            sk[4*l4+2] = fmaf(h1v, w.z, sk[4*l4+2]); sk[4*l4+3] = fmaf(h1v, w.w, sk[4*l4+3]);
        }
        #pragma unroll
        for (int l4 = 0; l4 < 8; l4++) {
            float4 w = s2[l4];
            sk[4*l4]   = fmaf(h2v, w.x, sk[4*l4]);   sk[4*l4+1] = fmaf(h2v, w.y, sk[4*l4+1]);
            sk[4*l4+2] = fmaf(h2v, w.z, sk[4*l4+2]); sk[4*l4+3] = fmaf(h2v, w.w, sk[4*l4+3]);
        }
        #pragma unroll
        for (int l4 = 0; l4 < 8; l4++) {
            float4 w = s3[l4];
            sk[4*l4]   = fmaf(h3v, w.x, sk[4*l4]);   sk[4*l4+1] = fmaf(h3v, w.y, sk[4*l4+1]);
            sk[4*l4+2] = fmaf(h3v, w.z, sk[4*l4+2]); sk[4*l4+3] = fmaf(h3v, w.w, sk[4*l4+3]);
        }
    }

    // tex path
    float zt[LAT];
    {
        const float4* z4 = (const float4*)(g_zt + r * LAT);
        #pragma unroll
        for (int i = 0; i < 8; i++) {
            float4 t = z4[i];
            zt[4*i] = t.x; zt[4*i+1] = t.y; zt[4*i+2] = t.z; zt[4*i+3] = t.w;
        }
    }
    float tx[DIN];
    #pragma unroll
    for (int l = 0; l < DIN; l++) tx[l] = 0.f;
    #pragma unroll
    for (int lp = 0; lp < LAT; lp++) {
        float ztl = zt[lp];
        const float4* t4 = (const float4*)(txws + lp * DIN);
        #pragma unroll
        for (int l4 = 0; l4 < 8; l4++) {
            float4 w = t4[l4];
            tx[4*l4]   = fmaf(ztl, w.x, tx[4*l4]);   tx[4*l4+1] = fmaf(ztl, w.y, tx[4*l4+1]);
            tx[4*l4+2] = fmaf(ztl, w.z, tx[4*l4+2]); tx[4*l4+3] = fmaf(ztl, w.w, tx[4*l4+3]);
        }
    }

    float4* xo = (float4*)(out + O_XHAT + r * DIN);
    #pragma unroll
    for (int l4 = 0; l4 < 8; l4++) {
        float4 t;
        #pragma unroll
        for (int q = 0; q < 4; q++) {
            int l = 4*l4 + q;
            float mlp  = __fadd_rn(o[l], rb2s[l]);
            float skp  = __fadd_rn(sk[l], skbs[l]);
            float base = __fadd_rn(mlp, skp);
            float texv = __fmul_rn(ts, __fadd_rn(tx[l], txbs[l]));
            ((float*)&t)[q] = __fadd_rn(base, texv);
        }
        xo[l4] = t;
    }
}

// ---------------- kernel D: vq_loss scalar ----------------
__global__ void kD(float* __restrict__ out, int full) {
    if (full) out[O_VQ] = (float)(1.25 * g_vq / ((double)Bsz * (double)LAT));
}

// ---------------- launch ----------------
extern "C" void kernel_launch(void* const* d_in, const int* in_sizes, int n_in,
                              void* d_out, int out_size) {
    const float* x    = (const float*)d_in[0];
    const float* fw1  = (const float*)d_in[1];
    const float* fb1  = (const float*)d_in[2];
    const float* fw2  = (const float*)d_in[3];
    const float* fb2  = (const float*)d_in[4];
    const float* vpw  = (const float*)d_in[5];
    const float* vpb  = (const float*)d_in[6];
    const float* cc   = (const float*)d_in[7];
    const float* cbk  = (const float*)d_in[8];
    const float* sfw1 = (const float*)d_in[9];
    const float* sfb1 = (const float*)d_in[10];
    const float* sfw2 = (const float*)d_in[11];
    const float* sfb2 = (const float*)d_in[12];
    const float* decw = (const float*)d_in[13];
    const float* decb = (const float*)d_in[14];
    const float* lrw  = (const float*)d_in[15];
    const float* lrb  = (const float*)d_in[16];
    const float* txw  = (const float*)d_in[17];
    const float* txb  = (const float*)d_in[18];
    const float* tsc  = (const float*)d_in[19];
    const float* rw1  = (const float*)d_in[20];
    const float* rb1  = (const float*)d_in[21];
    const float* rw2  = (const float*)d_in[22];
    const float* rb2  = (const float*)d_in[23];
    const float* skw  = (const float*)d_in[24];
    const float* skb  = (const float*)d_in[25];

    float* out = (float*)d_out;
    int full = (out_size >= O_TOTAL) ? 1 : 0;

    const int SMEM_A = (DIN*HID + HID*HID + HID*LAT + HID + HID + LAT + HID*256) * 4;
    const int SMEM_B = (NC*HID*LAT + NC*HID + KC*LAT + KC + NC*LAT + LAT*NC + LAT*MID
                        + MID*LAT + LAT*NC + MID + LAT + NC) * 4;
    const int SMEM_C = (HID*HID + HID*DIN + HID*DIN + LAT*DIN + HID + DIN + DIN + DIN) * 4;

    cudaFuncSetAttribute(kA, cudaFuncAttributeMaxDynamicSharedMemorySize, SMEM_A);
    cudaFuncSetAttribute(kB, cudaFuncAttributeMaxDynamicSharedMemorySize, SMEM_B);
    cudaFuncSetAttribute(kC, cudaFuncAttributeMaxDynamicSharedMemorySize, SMEM_C);

    kPrep<<<16, 256>>>(cbk);
    kA<<<Bsz / 256, 256, SMEM_A>>>(x, fw1, fb1, fw2, fb2, vpw, vpb);
    kB<<<Bsz / 256, 256, SMEM_B>>>(cc, cbk, sfw1, sfb1, sfw2, sfb2, decw, decb, lrw, lrb, out, full);
    kC<<<Bsz / 256, 256, SMEM_C>>>(rw1, rb1, rw2, rb2, skw, skb, txw, txb, tsc, out);
    kD<<<1, 1>>>(out, full);
}